// round 6
// baseline (speedup 1.0000x reference)
#include <cuda_runtime.h>
#include <cstdint>

// Problem constants
#define Bn   64
#define Cc   768
#define HW   676          // 26*26
#define Mm   32
#define NCLS 200
#define MC   (Mm*Cc)      // 24576
#define OFF_P   0
#define OFF_FM  (Bn*NCLS)                  // 12800
#define OFF_ATT (OFF_FM + Bn*MC)           // 12800 + 1572864

// Scratch (no allocation allowed -> device globals).
// NEVER pass these as host-side kernel arguments (host shadow address!) —
// reference them directly inside device code only.
__device__ float g_fmraw[Bn * MC];     // pooled bilinear features before sqrt
__device__ float g_scale[Bn];          // 1/max(||f||,eps)
__device__ float g_scale100[Bn];       // 100/max(||f||,eps)

// ---------------------------------------------------------------------------
// Kernel A: att_m[b,m,hw] = relu( sum_c fm[b,c,hw] * att_w[m,c] + att_b[m] )
// Only the first M=32 rows of att_w are ever used downstream.
// grid (6, 64), block 128. Each thread owns one hw position, 32 accumulators.
// W staged in smem in 64-c chunks, float4-granule XOR swizzle:
//   store loc(cp,m) = cp*32 + ((m>>2 ^ (cp&7))<<2) + (m&3)
//   read  float4 at cc*32 + j*4 (all lanes same addr -> broadcast)
// ---------------------------------------------------------------------------
__global__ __launch_bounds__(128) void k_att(
    const float* __restrict__ fmap, const float* __restrict__ attw,
    const float* __restrict__ attb, float* __restrict__ out_att)
{
    __shared__ __align__(16) float Ws[64 * 32];
    const int b  = blockIdx.y;
    const int hw = blockIdx.x * 128 + threadIdx.x;
    const int hwc = hw < HW ? hw : (HW - 1);

    float acc[32];
#pragma unroll
    for (int m = 0; m < 32; ++m) acc[m] = 0.f;

    for (int c0 = 0; c0 < Cc; c0 += 64) {
        __syncthreads();
#pragma unroll
        for (int i = 0; i < 16; ++i) {
            int e  = threadIdx.x + i * 128;     // 0..2047
            int cp = e & 63;
            int m  = e >> 6;                    // 0..31
            float val = attw[m * Cc + c0 + cp]; // coalesced along cp
            Ws[cp * 32 + (((m >> 2) ^ (cp & 7)) << 2) + (m & 3)] = val;
        }
        __syncthreads();

        const float* fp = fmap + ((size_t)b * Cc + c0) * HW + hwc;
        for (int cb = 0; cb < 4; ++cb) {        // 4 * 16 = 64 c's
#pragma unroll
            for (int u = 0; u < 16; ++u) {
                const int cc = cb * 16 + u;
                float v = fp[cc * HW];          // coalesced across threads
#pragma unroll
                for (int j = 0; j < 8; ++j) {
                    const int jm = j ^ (u & 7); // == j ^ (cc&7), compile-time
                    float4 w4 = *(const float4*)&Ws[cc * 32 + j * 4];
                    acc[4 * jm + 0] += w4.x * v;
                    acc[4 * jm + 1] += w4.y * v;
                    acc[4 * jm + 2] += w4.z * v;
                    acc[4 * jm + 3] += w4.w * v;
                }
            }
        }
    }

    if (hw < HW) {
        float* op = out_att + ((size_t)b * Mm) * HW + hw;
#pragma unroll
        for (int m = 0; m < 32; ++m) {
            float a = acc[m] + __ldg(&attb[m]);
            op[m * HW] = fmaxf(a, 0.f);
        }
    }
}

// ---------------------------------------------------------------------------
// Kernel B: g_fmraw[b,m,c] = (1/676) * sum_hw att[b,m,hw] * fm[b,c,hw]
// grid (24, 64), block 512 (16 warps).
// blockIdx.x: ct = x>>1 (c-quad tile of 16), mh = x&1 (which 16 m's).
// att half-tile (16 x 676, padded to 680) in static smem (43.5 KB).
// Each warp owns one c-quad: 1 LDS feeds 4 FFMAs; fm loads coalesced on hw.
// Writes g_fmraw DIRECTLY (device symbol; no host-passed pointer).
// ---------------------------------------------------------------------------
__global__ __launch_bounds__(512, 1) void k_pool(
    const float* __restrict__ fmap, const float* __restrict__ att)
{
    __shared__ float att_s[16 * 680];
    const int b  = blockIdx.y;
    const int ct = blockIdx.x >> 1;   // 0..11
    const int mh = blockIdx.x & 1;
    const int m0 = mh * 16;
    const int t  = threadIdx.x;

    for (int e = t; e < 16 * HW; e += 512) {
        int m = e / HW, hw = e - m * HW;
        att_s[m * 680 + hw] = att[((size_t)b * Mm + m0 + m) * HW + hw];
    }
    __syncthreads();

    const int w = t >> 5, lane = t & 31;
    const int c0 = (ct * 16 + w) * 4;           // 0..764
    float acc[16][4];
#pragma unroll
    for (int m = 0; m < 16; ++m)
#pragma unroll
        for (int j = 0; j < 4; ++j) acc[m][j] = 0.f;

    const float* fp = fmap + ((size_t)b * Cc + c0) * HW;

    // software-pipelined loads over hw
    int hw = lane;
    float nv0 = fp[0 * HW + hw], nv1 = fp[1 * HW + hw];
    float nv2 = fp[2 * HW + hw], nv3 = fp[3 * HW + hw];
    int hwc_cur = hw;

    for (int i = 0; i < 22; ++i) {
        float v0 = nv0, v1 = nv1, v2 = nv2, v3 = nv3;
        int hcur = hwc_cur;
        int hn = (i + 1) * 32 + lane;
        bool okn = (i + 1 < 22) && (hn < HW);
        int hnc = okn ? hn : 0;
        nv0 = okn ? fp[0 * HW + hnc] : 0.f;
        nv1 = okn ? fp[1 * HW + hnc] : 0.f;
        nv2 = okn ? fp[2 * HW + hnc] : 0.f;
        nv3 = okn ? fp[3 * HW + hnc] : 0.f;
        hwc_cur = hnc;
#pragma unroll
        for (int m = 0; m < 16; ++m) {
            float a = att_s[m * 680 + hcur];
            acc[m][0] += a * v0;
            acc[m][1] += a * v1;
            acc[m][2] += a * v2;
            acc[m][3] += a * v3;
        }
    }
    // Guard logic: iteration i consumes values preloaded during i-1 with
    // hn<HW check (i=0 preload uses hw=lane<676 always). Out-of-range lanes
    // carry v=0 and a valid smem index (0), contributing exactly 0. Correct.

    const float inv = 1.f / (float)HW;
#pragma unroll
    for (int m = 0; m < 16; ++m)
#pragma unroll
        for (int j = 0; j < 4; ++j) {
            float s = acc[m][j];
#pragma unroll
            for (int o = 16; o; o >>= 1) s += __shfl_xor_sync(0xffffffffu, s, o);
            if (lane == 0)
                g_fmraw[((size_t)b * Mm + m0 + m) * Cc + c0 + j] = s * inv;
        }
}

// ---------------------------------------------------------------------------
// Kernel C: f = sign(x)*sqrt(|x|+eps); store unnormalized f to out_fm;
// per-batch sumsq -> g_scale[b] = 1/max(||f||, eps), g_scale100 = 100*that.
// ---------------------------------------------------------------------------
__global__ __launch_bounds__(256) void k_ssqrt(float* __restrict__ out_fm)
{
    const int b = blockIdx.x;
    float ss = 0.f;
    for (int e = threadIdx.x; e < MC; e += 256) {
        float x = g_fmraw[b * MC + e];
        float f = (x == 0.f) ? 0.f : copysignf(sqrtf(fabsf(x) + 1e-12f), x);
        out_fm[b * MC + e] = f;
        ss += f * f;
    }
    __shared__ float red[8];
#pragma unroll
    for (int o = 16; o; o >>= 1) ss += __shfl_xor_sync(0xffffffffu, ss, o);
    if ((threadIdx.x & 31) == 0) red[threadIdx.x >> 5] = ss;
    __syncthreads();
    if (threadIdx.x < 8) {
        ss = red[threadIdx.x];
#pragma unroll
        for (int o = 4; o; o >>= 1) ss += __shfl_xor_sync(0xffu, ss, o);
        if (threadIdx.x == 0) {
            float nrm = sqrtf(ss);
            float s = 1.f / fmaxf(nrm, 1e-12f);
            g_scale[b] = s;
            g_scale100[b] = 100.f * s;
        }
    }
}

// p init with bias
__global__ __launch_bounds__(256) void k_p0(const float* __restrict__ fcb,
                                            float* __restrict__ out_p)
{
    int i = blockIdx.x * 256 + threadIdx.x;
    if (i < Bn * NCLS) out_p[i] = __ldg(&fcb[i % NCLS]);
}

// ---------------------------------------------------------------------------
// Kernel D: p[b,n] += sum_k f_unnorm[b,k]*(100/nrm_b) * fc_w[n,k]
// k-split tiled GEMM: grid (24 k-splits, 13 n-tiles of 16), block 256.
// smem tiles sfm[64][33], sw[16][32]; thread = (b = t&63, n-group = t>>6 of 4).
// atomicAdd partial sums into bias-initialized p.
// ---------------------------------------------------------------------------
__global__ __launch_bounds__(256) void k_fc(
    const float* __restrict__ fmn, const float* __restrict__ fcw,
    float* __restrict__ out_p)
{
    __shared__ float sfm[64 * 33];
    __shared__ float sw[16 * 32];
    const int k0 = blockIdx.x * 1024;
    const int n0 = blockIdx.y * 16;
    const int t  = threadIdx.x;
    const int tb = t & 63, tg = t >> 6;

    float s100[8];
#pragma unroll
    for (int i = 0; i < 8; ++i) s100[i] = g_scale100[(t + i * 256) >> 5];

    float acc0 = 0.f, acc1 = 0.f, acc2 = 0.f, acc3 = 0.f;

    for (int kb = 0; kb < 1024; kb += 32) {
        __syncthreads();
#pragma unroll
        for (int i = 0; i < 8; ++i) {
            int e = t + i * 256;
            int bb = e >> 5, kk = e & 31;
            sfm[bb * 33 + kk] = fmn[bb * MC + k0 + kb + kk] * s100[i];
        }
#pragma unroll
        for (int i = 0; i < 2; ++i) {
            int e = t + i * 256;
            int nn = e >> 5, kk = e & 31;
            int n = n0 + nn;
            sw[nn * 32 + kk] = (n < NCLS) ? fcw[(size_t)n * MC + k0 + kb + kk] : 0.f;
        }
        __syncthreads();
#pragma unroll
        for (int kk = 0; kk < 32; ++kk) {
            float v = sfm[tb * 33 + kk];
            acc0 += v * sw[(tg * 4 + 0) * 32 + kk];
            acc1 += v * sw[(tg * 4 + 1) * 32 + kk];
            acc2 += v * sw[(tg * 4 + 2) * 32 + kk];
            acc3 += v * sw[(tg * 4 + 3) * 32 + kk];
        }
    }
    int n = n0 + tg * 4;
    if (n + 0 < NCLS) atomicAdd(&out_p[tb * NCLS + n + 0], acc0);
    if (n + 1 < NCLS) atomicAdd(&out_p[tb * NCLS + n + 1], acc1);
    if (n + 2 < NCLS) atomicAdd(&out_p[tb * NCLS + n + 2], acc2);
    if (n + 3 < NCLS) atomicAdd(&out_p[tb * NCLS + n + 3], acc3);
}

// normalize fm in place (after k_fc has consumed the unnormalized values)
__global__ __launch_bounds__(256) void k_norm(float* __restrict__ out_fm)
{
    int i = blockIdx.x * 256 + threadIdx.x;
    if (i < Bn * MC) out_fm[i] *= g_scale[i / MC];
}

// ---------------------------------------------------------------------------
extern "C" void kernel_launch(void* const* d_in, const int* in_sizes, int n_in,
                              void* d_out, int out_size)
{
    const float* fmap = (const float*)d_in[0];
    const float* attw = (const float*)d_in[1];
    const float* attb = (const float*)d_in[2];
    const float* fcw  = (const float*)d_in[3];
    const float* fcb  = (const float*)d_in[4];
    float* out     = (float*)d_out;
    float* out_p   = out + OFF_P;
    float* out_fm  = out + OFF_FM;
    float* out_att = out + OFF_ATT;
    (void)in_sizes; (void)n_in; (void)out_size;

    k_att <<<dim3(6, 64),  128>>>(fmap, attw, attb, out_att);
    k_pool<<<dim3(24, 64), 512>>>(fmap, out_att);
    k_ssqrt<<<Bn, 256>>>(out_fm);
    k_p0  <<<(Bn * NCLS + 255) / 256, 256>>>(fcb, out_p);
    k_fc  <<<dim3(24, 13), 256>>>(out_fm, fcw, out_p);
    k_norm<<<(Bn * MC + 255) / 256, 256>>>(out_fm);
}